// round 16
// baseline (speedup 1.0000x reference)
#include <cuda_runtime.h>
#include <cuda_fp16.h>
#include <math.h>

// Cone-beam forward projection, dual-layout fp16 packed volume.
//
// Layout A: g_volA[z][y][x], cell = 8 halves (b0,b1) x (z0,z1) x (x0,x1).
// Layout B: g_volB[z][x][y], cell = 8 halves (b0,b1) x (z0,z1) x (y0,y1).
// fp_kernel picks the layout whose fast axis matches the warp's lane-varying
// world axis -> lane-contiguous 16B-cell gathers at every angle.
// Sample range split into guaranteed-interior part (no mask/clamp, manual
// 2-sample unroll, 4 back-to-back LDG.128 for MLP) + masked edge samples.
// Interp: x/y-lerp in half2, z-lerp + accumulate in packed f32x2.
// Ray split into two half-rays (gridDim.y=2); combined via atomicAdd.
// Prep: 2-z-slab smem-tiled pass builds BOTH layouts and zeroes the output.
// vol in: [B=2, Z=96, Y=96, X=96] fp32. out: [B=2, A=48, V=96, U=96] fp32.

#define NZ 96
#define NY 96
#define NX 96
#define NV 96
#define NU 96
#define NA 48
#define NS 96

#define DSO 500.0f
#define DSD 1000.0f
#define DDET 2.0f

#define STEP 1.7320508075688772f
#define T0   416.86156123669393f

#define VOL_N (NZ * NY * NX)     // 884736
#define SROW 96
#define SZ (NX * NY)             // 9216
#define NRAY (NA * NV * NU)      // 442368
#define OUT4 ((2 * NRAY) / 4)    // 221184 float4s
#define NPREPBLK (3 * 3 * 48)    // 432
#define ZPB ((OUT4 + NPREPBLK - 1) / NPREPBLK)   // 512 float4 per prep block

__device__ uint4 g_volA[VOL_N];  // 14.2 MB
__device__ uint4 g_volB[VOL_N];  // 14.2 MB

typedef unsigned long long u64;

static __device__ __forceinline__ unsigned h2u(__half2 h) {
    union { __half2 h; unsigned u; } cvt; cvt.h = h; return cvt.u;
}
static __device__ __forceinline__ __half2 u2h(unsigned u) {
    union { unsigned u; __half2 h; } cvt; cvt.u = u; return cvt.h;
}
static __device__ __forceinline__ u64 pk2(float lo, float hi) {
    u64 r;
    asm("mov.b64 %0, {%1, %2};" : "=l"(r) : "f"(lo), "f"(hi));
    return r;
}
static __device__ __forceinline__ u64 fma2_(u64 a, u64 b, u64 c) {
    u64 d;
    asm("fma.rn.f32x2 %0, %1, %2, %3;" : "=l"(d) : "l"(a), "l"(b), "l"(c));
    return d;
}

// ---------------------------------------------------------------------------
// Tiled prep (unchanged): builds both layouts, zeroes output.
// ---------------------------------------------------------------------------
__global__ void __launch_bounds__(256) prep_tiled(const float* __restrict__ vol,
                                                  float4* __restrict__ outz) {
    __shared__ unsigned s[3][33][35];

    int x0t = blockIdx.x * 32;
    int y0t = blockIdx.y * 32;
    int zb  = blockIdx.z * 2;
    int z2  = min(zb + 2, NZ - 1);

    {
        int blk = (blockIdx.z * gridDim.y + blockIdx.y) * gridDim.x + blockIdx.x;
        int base = blk * ZPB + threadIdx.x;
        const float4 z4 = make_float4(0.f, 0.f, 0.f, 0.f);
        #pragma unroll
        for (int r = 0; r < ZPB / 256; r++) {
            int j = base + r * 256;
            if (j < OUT4) outz[j] = z4;
        }
    }

    const float* b0 = vol;
    const float* b1 = vol + VOL_N;

    int tid = threadIdx.x;

    {
        int yl = tid / 33;
        int xl = tid - yl * 33;
        for (int k = tid; k < 33 * 33; k += 256) {
            int gy = min(y0t + yl, NY - 1);
            int gx = min(x0t + xl, NX - 1);
            int base = gy * NX + gx;
            int i0 = zb * SZ + base;
            int i1 = (zb + 1) * SZ + base;
            int i2 = z2 * SZ + base;
            s[0][yl][xl] = h2u(__floats2half2_rn(b0[i0], b1[i0]));
            s[1][yl][xl] = h2u(__floats2half2_rn(b0[i1], b1[i1]));
            s[2][yl][xl] = h2u(__floats2half2_rn(b0[i2], b1[i2]));
            yl += 7; xl += 25;
            if (xl >= 33) { xl -= 33; yl += 1; }
        }
    }
    __syncthreads();

    int tx = tid & 31;
    int ty = tid >> 5;

    #pragma unroll
    for (int dz = 0; dz < 2; dz++) {
        int z = zb + dz;

        for (int yr = ty; yr < 32; yr += 8) {
            uint4 q;
            q.x = s[dz][yr][tx];
            q.y = s[dz][yr][tx + 1];
            q.z = s[dz + 1][yr][tx];
            q.w = s[dz + 1][yr][tx + 1];
            g_volA[z * SZ + (y0t + yr) * NX + (x0t + tx)] = q;
        }

        for (int xr = ty; xr < 32; xr += 8) {
            uint4 q;
            q.x = s[dz][tx][xr];
            q.y = s[dz][tx + 1][xr];
            q.z = s[dz + 1][tx][xr];
            q.w = s[dz + 1][tx + 1][xr];
            g_volB[z * SZ + (x0t + xr) * NY + (y0t + tx)] = q;
        }
    }
}

// interp one interior sample (no mask): address + x/y half lerp + f32x2 tail
static __device__ __forceinline__ void interp1(const uint4* __restrict__ g,
                                               float x, float y, float z,
                                               u64 one2, u64 neg12, u64& acc) {
    int x0 = min((int)x, NX - 2);
    int y0 = min((int)y, NY - 2);
    int z0 = min((int)z, NZ - 2);
    float fx = x - (float)x0;
    float fy = y - (float)y0;
    float fz = z - (float)z0;

    const uint4* p = g + (z0 * SZ + y0 * SROW + x0);
    uint4 r0 = __ldg(p);
    uint4 r1 = __ldg(p + SROW);

    __half2 fx2 = __float2half2_rn(fx);
    __half2 xz0y0 = __hfma2(fx2, __hsub2(u2h(r0.y), u2h(r0.x)), u2h(r0.x));
    __half2 xz1y0 = __hfma2(fx2, __hsub2(u2h(r0.w), u2h(r0.z)), u2h(r0.z));
    __half2 xz0y1 = __hfma2(fx2, __hsub2(u2h(r1.y), u2h(r1.x)), u2h(r1.x));
    __half2 xz1y1 = __hfma2(fx2, __hsub2(u2h(r1.w), u2h(r1.z)), u2h(r1.z));

    __half2 fy2 = __float2half2_rn(fy);
    __half2 yz0 = __hfma2(fy2, __hsub2(xz0y1, xz0y0), xz0y0);
    __half2 yz1 = __hfma2(fy2, __hsub2(xz1y1, xz1y0), xz1y0);

    float2 f0 = __half22float2(yz0);
    float2 f1 = __half22float2(yz1);
    u64 Z0 = pk2(f0.x, f0.y);
    u64 Z1 = pk2(f1.x, f1.y);
    u64 fz2 = pk2(fz, fz);

    u64 d = fma2_(neg12, Z0, Z1);
    acc = fma2_(fz2, d, fma2_(one2, Z0, acc));
}

// masked edge sample (clamped address, mask folded into accumulate)
static __device__ __forceinline__ void interp_edge(const uint4* __restrict__ g,
                                                   float x, float y, float z,
                                                   u64 one2, u64 neg12, u64& acc) {
    float mn = fminf(fminf(x, y), z);
    float mx = fmaxf(fmaxf(x, y), z);
    float m = ((mn >= 0.0f) & (mx <= 95.0f)) ? 1.0f : 0.0f;
    if (m == 0.0f) return;
    interp1(g, x, y, z, one2, neg12, acc);
}

__global__ void __launch_bounds__(256) fp_kernel(float* __restrict__ out) {
    int idx = blockIdx.x * blockDim.x + threadIdx.x;   // ray id
    int half = blockIdx.y;                             // 0 or 1
    int u = idx % NU;
    int v = (idx / NU) % NV;
    int a = idx / (NU * NV);

    float theta = (float)a * (6.2831853071795864769f / (float)NA);
    float s = sinf(theta);
    float c = cosf(theta);

    float srcx = DSO * c;
    float srcy = DSO * s;

    float uu = ((float)u - (NU - 1) * 0.5f) * DDET;
    float vv = ((float)v - (NV - 1) * 0.5f) * DDET;

    float px = -(DSD - DSO) * c - uu * s;
    float py = -(DSD - DSO) * s + uu * c;
    float pz = vv;

    float dx = px - srcx;
    float dy = py - srcy;
    float dz = pz;
    float inv = rsqrtf(fmaf(dx, dx, fmaf(dy, dy, dz * dz)));
    dx *= inv; dy *= inv; dz *= inv;

    // ray/box slab test, box = [-47.5, 47.5]^3 world ([0,95] voxel)
    const float H = 47.5f;
    float ix_ = 1.0f / dx, iy_ = 1.0f / dy, iz_ = 1.0f / dz;
    float tx1 = (-H - srcx) * ix_, tx2 = (H - srcx) * ix_;
    float ty1 = (-H - srcy) * iy_, ty2 = (H - srcy) * iy_;
    float tz1 = (-H) * iz_,        tz2 = (H) * iz_;
    float tmin = fmaxf(fmaxf(fminf(tx1, tx2), fminf(ty1, ty2)), fminf(tz1, tz2));
    float tmax = fminf(fminf(fmaxf(tx1, tx2), fmaxf(ty1, ty2)), fmaxf(tz1, tz2));

    // outer (padded) and interior (guaranteed in-bounds) sample ranges
    int i0 = 0, i1 = 0, ib = 0, ie = 0;
    if (tmax > tmin) {
        float raw0 = (tmin - T0) / STEP - 0.5f;
        float raw1 = (tmax - T0) / STEP - 0.5f;
        i0 = max(0, (int)floorf(raw0) - 1);
        i1 = min(NS, (int)ceilf(raw1) + 2);
        ib = max(i0, (int)ceilf(raw0) + 1);    // strict interior: 1-sample margin
        ie = min(i1, (int)floorf(raw1));       // [ib, ie) interior
        if (ie < ib) { ib = i0; ie = i0; }     // degenerate: all edge
    }

    // this half-ray's slice of [i0, i1)
    int mid = (i0 + i1) >> 1;
    int sBeg = half ? mid : i0;
    int sEnd = half ? i1 : mid;
    // intersect with interior
    int intBeg = max(sBeg, ib);
    int intEnd = min(sEnd, ie);
    if (intEnd < intBeg) { intBeg = sBeg; intEnd = sBeg; }

    bool useA = fabsf(s) >= fabsf(c);
    const uint4* __restrict__ g = useA ? g_volA : g_volB;

    float fdx = useA ? dx : dy;
    float fdy = useA ? dy : dx;
    float cx = (useA ? srcx : srcy) + 47.5f;
    float cy = (useA ? srcy : srcx) + 47.5f;
    float cz = 47.5f;

    u64 acc = pk2(0.0f, 0.0f);        // (batch0, batch1)
    const u64 one2  = pk2(1.0f, 1.0f);
    const u64 neg12 = pk2(-1.0f, -1.0f);

    // ---- leading edge samples [sBeg, intBeg) : masked ----
    for (int i = sBeg; i < intBeg; i++) {
        float t = fmaf((float)i + 0.5f, STEP, T0);
        interp_edge(g, fmaf(fdx, t, cx), fmaf(fdy, t, cy), fmaf(dz, t, cz),
                    one2, neg12, acc);
    }

    // ---- interior: unmasked, pair-unrolled, 4 back-to-back loads ----
    int i = intBeg;
    for (; i + 1 < intEnd; i += 2) {
        float ta = fmaf((float)i + 0.5f, STEP, T0);
        float tb = fmaf((float)i + 1.5f, STEP, T0);
        float xa = fmaf(fdx, ta, cx), ya = fmaf(fdy, ta, cy), za = fmaf(dz, ta, cz);
        float xb = fmaf(fdx, tb, cx), yb = fmaf(fdy, tb, cy), zb = fmaf(dz, tb, cz);

        int xa0 = min((int)xa, NX - 2), ya0 = min((int)ya, NY - 2), za0 = min((int)za, NZ - 2);
        int xb0 = min((int)xb, NX - 2), yb0 = min((int)yb, NY - 2), zb0 = min((int)zb, NZ - 2);

        const uint4* pa = g + (za0 * SZ + ya0 * SROW + xa0);
        const uint4* pb = g + (zb0 * SZ + yb0 * SROW + xb0);
        uint4 ra0 = __ldg(pa);
        uint4 ra1 = __ldg(pa + SROW);
        uint4 rb0 = __ldg(pb);
        uint4 rb1 = __ldg(pb + SROW);

        float fxa = xa - (float)xa0, fya = ya - (float)ya0, fza = za - (float)za0;
        float fxb = xb - (float)xb0, fyb = yb - (float)yb0, fzb = zb - (float)zb0;

        // sample a
        {
            __half2 fx2 = __float2half2_rn(fxa);
            __half2 p00 = __hfma2(fx2, __hsub2(u2h(ra0.y), u2h(ra0.x)), u2h(ra0.x));
            __half2 p10 = __hfma2(fx2, __hsub2(u2h(ra0.w), u2h(ra0.z)), u2h(ra0.z));
            __half2 p01 = __hfma2(fx2, __hsub2(u2h(ra1.y), u2h(ra1.x)), u2h(ra1.x));
            __half2 p11 = __hfma2(fx2, __hsub2(u2h(ra1.w), u2h(ra1.z)), u2h(ra1.z));
            __half2 fy2 = __float2half2_rn(fya);
            __half2 yz0 = __hfma2(fy2, __hsub2(p01, p00), p00);
            __half2 yz1 = __hfma2(fy2, __hsub2(p11, p10), p10);
            float2 f0 = __half22float2(yz0);
            float2 f1 = __half22float2(yz1);
            u64 Z0 = pk2(f0.x, f0.y);
            u64 Z1 = pk2(f1.x, f1.y);
            u64 fz2 = pk2(fza, fza);
            u64 d = fma2_(neg12, Z0, Z1);
            acc = fma2_(fz2, d, fma2_(one2, Z0, acc));
        }
        // sample b
        {
            __half2 fx2 = __float2half2_rn(fxb);
            __half2 p00 = __hfma2(fx2, __hsub2(u2h(rb0.y), u2h(rb0.x)), u2h(rb0.x));
            __half2 p10 = __hfma2(fx2, __hsub2(u2h(rb0.w), u2h(rb0.z)), u2h(rb0.z));
            __half2 p01 = __hfma2(fx2, __hsub2(u2h(rb1.y), u2h(rb1.x)), u2h(rb1.x));
            __half2 p11 = __hfma2(fx2, __hsub2(u2h(rb1.w), u2h(rb1.z)), u2h(rb1.z));
            __half2 fy2 = __float2half2_rn(fyb);
            __half2 yz0 = __hfma2(fy2, __hsub2(p01, p00), p00);
            __half2 yz1 = __hfma2(fy2, __hsub2(p11, p10), p10);
            float2 f0 = __half22float2(yz0);
            float2 f1 = __half22float2(yz1);
            u64 Z0 = pk2(f0.x, f0.y);
            u64 Z1 = pk2(f1.x, f1.y);
            u64 fz2 = pk2(fzb, fzb);
            u64 d = fma2_(neg12, Z0, Z1);
            acc = fma2_(fz2, d, fma2_(one2, Z0, acc));
        }
    }
    if (i < intEnd) {
        float t = fmaf((float)i + 0.5f, STEP, T0);
        interp1(g, fmaf(fdx, t, cx), fmaf(fdy, t, cy), fmaf(dz, t, cz),
                one2, neg12, acc);
        i++;
    }

    // ---- trailing edge samples [max(intEnd, sBeg), sEnd) : masked ----
    for (int j = max(intEnd, sBeg); j < sEnd; j++) {
        if (j >= intBeg && j < intEnd) continue;   // already done
        float t = fmaf((float)j + 0.5f, STEP, T0);
        interp_edge(g, fmaf(fdx, t, cx), fmaf(fdy, t, cy), fmaf(dz, t, cz),
                    one2, neg12, acc);
    }

    float acc0, acc1;
    asm("mov.b64 {%0, %1}, %2;" : "=f"(acc0), "=f"(acc1) : "l"(acc));

    atomicAdd(&out[idx],        acc0 * STEP);
    atomicAdd(&out[idx + NRAY], acc1 * STEP);
}

extern "C" void kernel_launch(void* const* d_in, const int* in_sizes, int n_in,
                              void* d_out, int out_size) {
    const float* vol = (const float*)d_in[0];
    float* out = (float*)d_out;

    {
        dim3 grid(NX / 32, NY / 32, NZ / 2);   // (3,3,48)
        prep_tiled<<<grid, 256>>>(vol, (float4*)out);
    }
    {
        dim3 grid(NRAY / 256, 2);          // (1728, 2)
        fp_kernel<<<grid, 256>>>(out);
    }
}

// round 17
// speedup vs baseline: 1.0230x; 1.0230x over previous
#include <cuda_runtime.h>
#include <cuda_fp16.h>
#include <math.h>

// Cone-beam forward projection, dual-layout fp16 packed volume.
// Identical to R16 except fp_kernel uses __launch_bounds__(256, 4) to give
// ptxas a 64-register budget so the interior pair-loop's 4 LDG.128s can be
// kept live simultaneously (front-batched) instead of serialized.
// vol in: [B=2, Z=96, Y=96, X=96] fp32. out: [B=2, A=48, V=96, U=96] fp32.

#define NZ 96
#define NY 96
#define NX 96
#define NV 96
#define NU 96
#define NA 48
#define NS 96

#define DSO 500.0f
#define DSD 1000.0f
#define DDET 2.0f

#define STEP 1.7320508075688772f
#define T0   416.86156123669393f

#define VOL_N (NZ * NY * NX)     // 884736
#define SROW 96
#define SZ (NX * NY)             // 9216
#define NRAY (NA * NV * NU)      // 442368
#define OUT4 ((2 * NRAY) / 4)    // 221184 float4s
#define NPREPBLK (3 * 3 * 48)    // 432
#define ZPB ((OUT4 + NPREPBLK - 1) / NPREPBLK)   // 512 float4 per prep block

__device__ uint4 g_volA[VOL_N];  // 14.2 MB
__device__ uint4 g_volB[VOL_N];  // 14.2 MB

typedef unsigned long long u64;

static __device__ __forceinline__ unsigned h2u(__half2 h) {
    union { __half2 h; unsigned u; } cvt; cvt.h = h; return cvt.u;
}
static __device__ __forceinline__ __half2 u2h(unsigned u) {
    union { unsigned u; __half2 h; } cvt; cvt.u = u; return cvt.h;
}
static __device__ __forceinline__ u64 pk2(float lo, float hi) {
    u64 r;
    asm("mov.b64 %0, {%1, %2};" : "=l"(r) : "f"(lo), "f"(hi));
    return r;
}
static __device__ __forceinline__ u64 fma2_(u64 a, u64 b, u64 c) {
    u64 d;
    asm("fma.rn.f32x2 %0, %1, %2, %3;" : "=l"(d) : "l"(a), "l"(b), "l"(c));
    return d;
}

// ---------------------------------------------------------------------------
// Tiled prep (unchanged): builds both layouts, zeroes output.
// ---------------------------------------------------------------------------
__global__ void __launch_bounds__(256) prep_tiled(const float* __restrict__ vol,
                                                  float4* __restrict__ outz) {
    __shared__ unsigned s[3][33][35];

    int x0t = blockIdx.x * 32;
    int y0t = blockIdx.y * 32;
    int zb  = blockIdx.z * 2;
    int z2  = min(zb + 2, NZ - 1);

    {
        int blk = (blockIdx.z * gridDim.y + blockIdx.y) * gridDim.x + blockIdx.x;
        int base = blk * ZPB + threadIdx.x;
        const float4 z4 = make_float4(0.f, 0.f, 0.f, 0.f);
        #pragma unroll
        for (int r = 0; r < ZPB / 256; r++) {
            int j = base + r * 256;
            if (j < OUT4) outz[j] = z4;
        }
    }

    const float* b0 = vol;
    const float* b1 = vol + VOL_N;

    int tid = threadIdx.x;

    {
        int yl = tid / 33;
        int xl = tid - yl * 33;
        for (int k = tid; k < 33 * 33; k += 256) {
            int gy = min(y0t + yl, NY - 1);
            int gx = min(x0t + xl, NX - 1);
            int base = gy * NX + gx;
            int i0 = zb * SZ + base;
            int i1 = (zb + 1) * SZ + base;
            int i2 = z2 * SZ + base;
            s[0][yl][xl] = h2u(__floats2half2_rn(b0[i0], b1[i0]));
            s[1][yl][xl] = h2u(__floats2half2_rn(b0[i1], b1[i1]));
            s[2][yl][xl] = h2u(__floats2half2_rn(b0[i2], b1[i2]));
            yl += 7; xl += 25;
            if (xl >= 33) { xl -= 33; yl += 1; }
        }
    }
    __syncthreads();

    int tx = tid & 31;
    int ty = tid >> 5;

    #pragma unroll
    for (int dz = 0; dz < 2; dz++) {
        int z = zb + dz;

        for (int yr = ty; yr < 32; yr += 8) {
            uint4 q;
            q.x = s[dz][yr][tx];
            q.y = s[dz][yr][tx + 1];
            q.z = s[dz + 1][yr][tx];
            q.w = s[dz + 1][yr][tx + 1];
            g_volA[z * SZ + (y0t + yr) * NX + (x0t + tx)] = q;
        }

        for (int xr = ty; xr < 32; xr += 8) {
            uint4 q;
            q.x = s[dz][tx][xr];
            q.y = s[dz][tx + 1][xr];
            q.z = s[dz + 1][tx][xr];
            q.w = s[dz + 1][tx + 1][xr];
            g_volB[z * SZ + (x0t + xr) * NY + (y0t + tx)] = q;
        }
    }
}

// interp one interior sample (no mask)
static __device__ __forceinline__ void interp1(const uint4* __restrict__ g,
                                               float x, float y, float z,
                                               u64 one2, u64 neg12, u64& acc) {
    int x0 = min((int)x, NX - 2);
    int y0 = min((int)y, NY - 2);
    int z0 = min((int)z, NZ - 2);
    float fx = x - (float)x0;
    float fy = y - (float)y0;
    float fz = z - (float)z0;

    const uint4* p = g + (z0 * SZ + y0 * SROW + x0);
    uint4 r0 = __ldg(p);
    uint4 r1 = __ldg(p + SROW);

    __half2 fx2 = __float2half2_rn(fx);
    __half2 xz0y0 = __hfma2(fx2, __hsub2(u2h(r0.y), u2h(r0.x)), u2h(r0.x));
    __half2 xz1y0 = __hfma2(fx2, __hsub2(u2h(r0.w), u2h(r0.z)), u2h(r0.z));
    __half2 xz0y1 = __hfma2(fx2, __hsub2(u2h(r1.y), u2h(r1.x)), u2h(r1.x));
    __half2 xz1y1 = __hfma2(fx2, __hsub2(u2h(r1.w), u2h(r1.z)), u2h(r1.z));

    __half2 fy2 = __float2half2_rn(fy);
    __half2 yz0 = __hfma2(fy2, __hsub2(xz0y1, xz0y0), xz0y0);
    __half2 yz1 = __hfma2(fy2, __hsub2(xz1y1, xz1y0), xz1y0);

    float2 f0 = __half22float2(yz0);
    float2 f1 = __half22float2(yz1);
    u64 Z0 = pk2(f0.x, f0.y);
    u64 Z1 = pk2(f1.x, f1.y);
    u64 fz2 = pk2(fz, fz);

    u64 d = fma2_(neg12, Z0, Z1);
    acc = fma2_(fz2, d, fma2_(one2, Z0, acc));
}

// masked edge sample
static __device__ __forceinline__ void interp_edge(const uint4* __restrict__ g,
                                                   float x, float y, float z,
                                                   u64 one2, u64 neg12, u64& acc) {
    float mn = fminf(fminf(x, y), z);
    float mx = fmaxf(fmaxf(x, y), z);
    float m = ((mn >= 0.0f) & (mx <= 95.0f)) ? 1.0f : 0.0f;
    if (m == 0.0f) return;
    interp1(g, x, y, z, one2, neg12, acc);
}

__global__ void __launch_bounds__(256, 4) fp_kernel(float* __restrict__ out) {
    int idx = blockIdx.x * blockDim.x + threadIdx.x;   // ray id
    int half = blockIdx.y;                             // 0 or 1
    int u = idx % NU;
    int v = (idx / NU) % NV;
    int a = idx / (NU * NV);

    float theta = (float)a * (6.2831853071795864769f / (float)NA);
    float s = sinf(theta);
    float c = cosf(theta);

    float srcx = DSO * c;
    float srcy = DSO * s;

    float uu = ((float)u - (NU - 1) * 0.5f) * DDET;
    float vv = ((float)v - (NV - 1) * 0.5f) * DDET;

    float px = -(DSD - DSO) * c - uu * s;
    float py = -(DSD - DSO) * s + uu * c;
    float pz = vv;

    float dx = px - srcx;
    float dy = py - srcy;
    float dz = pz;
    float inv = rsqrtf(fmaf(dx, dx, fmaf(dy, dy, dz * dz)));
    dx *= inv; dy *= inv; dz *= inv;

    // ray/box slab test, box = [-47.5, 47.5]^3 world ([0,95] voxel)
    const float H = 47.5f;
    float ix_ = 1.0f / dx, iy_ = 1.0f / dy, iz_ = 1.0f / dz;
    float tx1 = (-H - srcx) * ix_, tx2 = (H - srcx) * ix_;
    float ty1 = (-H - srcy) * iy_, ty2 = (H - srcy) * iy_;
    float tz1 = (-H) * iz_,        tz2 = (H) * iz_;
    float tmin = fmaxf(fmaxf(fminf(tx1, tx2), fminf(ty1, ty2)), fminf(tz1, tz2));
    float tmax = fminf(fminf(fmaxf(tx1, tx2), fmaxf(ty1, ty2)), fmaxf(tz1, tz2));

    // outer (padded) and interior (guaranteed in-bounds) sample ranges
    int i0 = 0, i1 = 0, ib = 0, ie = 0;
    if (tmax > tmin) {
        float raw0 = (tmin - T0) / STEP - 0.5f;
        float raw1 = (tmax - T0) / STEP - 0.5f;
        i0 = max(0, (int)floorf(raw0) - 1);
        i1 = min(NS, (int)ceilf(raw1) + 2);
        ib = max(i0, (int)ceilf(raw0) + 1);    // strict interior: 1-sample margin
        ie = min(i1, (int)floorf(raw1));       // [ib, ie) interior
        if (ie < ib) { ib = i0; ie = i0; }
    }

    int mid = (i0 + i1) >> 1;
    int sBeg = half ? mid : i0;
    int sEnd = half ? i1 : mid;
    int intBeg = max(sBeg, ib);
    int intEnd = min(sEnd, ie);
    if (intEnd < intBeg) { intBeg = sBeg; intEnd = sBeg; }

    bool useA = fabsf(s) >= fabsf(c);
    const uint4* __restrict__ g = useA ? g_volA : g_volB;

    float fdx = useA ? dx : dy;
    float fdy = useA ? dy : dx;
    float cx = (useA ? srcx : srcy) + 47.5f;
    float cy = (useA ? srcy : srcx) + 47.5f;
    float cz = 47.5f;

    u64 acc = pk2(0.0f, 0.0f);        // (batch0, batch1)
    const u64 one2  = pk2(1.0f, 1.0f);
    const u64 neg12 = pk2(-1.0f, -1.0f);

    // ---- leading edge samples [sBeg, intBeg) : masked ----
    for (int i = sBeg; i < intBeg; i++) {
        float t = fmaf((float)i + 0.5f, STEP, T0);
        interp_edge(g, fmaf(fdx, t, cx), fmaf(fdy, t, cy), fmaf(dz, t, cz),
                    one2, neg12, acc);
    }

    // ---- interior: unmasked, pair-unrolled, 4 back-to-back loads ----
    int i = intBeg;
    for (; i + 1 < intEnd; i += 2) {
        float ta = fmaf((float)i + 0.5f, STEP, T0);
        float tb = fmaf((float)i + 1.5f, STEP, T0);
        float xa = fmaf(fdx, ta, cx), ya = fmaf(fdy, ta, cy), za = fmaf(dz, ta, cz);
        float xb = fmaf(fdx, tb, cx), yb = fmaf(fdy, tb, cy), zb = fmaf(dz, tb, cz);

        int xa0 = min((int)xa, NX - 2), ya0 = min((int)ya, NY - 2), za0 = min((int)za, NZ - 2);
        int xb0 = min((int)xb, NX - 2), yb0 = min((int)yb, NY - 2), zb0 = min((int)zb, NZ - 2);

        const uint4* pa = g + (za0 * SZ + ya0 * SROW + xa0);
        const uint4* pb = g + (zb0 * SZ + yb0 * SROW + xb0);
        uint4 ra0 = __ldg(pa);
        uint4 ra1 = __ldg(pa + SROW);
        uint4 rb0 = __ldg(pb);
        uint4 rb1 = __ldg(pb + SROW);

        float fxa = xa - (float)xa0, fya = ya - (float)ya0, fza = za - (float)za0;
        float fxb = xb - (float)xb0, fyb = yb - (float)yb0, fzb = zb - (float)zb0;

        // sample a
        {
            __half2 fx2 = __float2half2_rn(fxa);
            __half2 p00 = __hfma2(fx2, __hsub2(u2h(ra0.y), u2h(ra0.x)), u2h(ra0.x));
            __half2 p10 = __hfma2(fx2, __hsub2(u2h(ra0.w), u2h(ra0.z)), u2h(ra0.z));
            __half2 p01 = __hfma2(fx2, __hsub2(u2h(ra1.y), u2h(ra1.x)), u2h(ra1.x));
            __half2 p11 = __hfma2(fx2, __hsub2(u2h(ra1.w), u2h(ra1.z)), u2h(ra1.z));
            __half2 fy2 = __float2half2_rn(fya);
            __half2 yz0 = __hfma2(fy2, __hsub2(p01, p00), p00);
            __half2 yz1 = __hfma2(fy2, __hsub2(p11, p10), p10);
            float2 f0 = __half22float2(yz0);
            float2 f1 = __half22float2(yz1);
            u64 Z0 = pk2(f0.x, f0.y);
            u64 Z1 = pk2(f1.x, f1.y);
            u64 fz2 = pk2(fza, fza);
            u64 d = fma2_(neg12, Z0, Z1);
            acc = fma2_(fz2, d, fma2_(one2, Z0, acc));
        }
        // sample b
        {
            __half2 fx2 = __float2half2_rn(fxb);
            __half2 p00 = __hfma2(fx2, __hsub2(u2h(rb0.y), u2h(rb0.x)), u2h(rb0.x));
            __half2 p10 = __hfma2(fx2, __hsub2(u2h(rb0.w), u2h(rb0.z)), u2h(rb0.z));
            __half2 p01 = __hfma2(fx2, __hsub2(u2h(rb1.y), u2h(rb1.x)), u2h(rb1.x));
            __half2 p11 = __hfma2(fx2, __hsub2(u2h(rb1.w), u2h(rb1.z)), u2h(rb1.z));
            __half2 fy2 = __float2half2_rn(fyb);
            __half2 yz0 = __hfma2(fy2, __hsub2(p01, p00), p00);
            __half2 yz1 = __hfma2(fy2, __hsub2(p11, p10), p10);
            float2 f0 = __half22float2(yz0);
            float2 f1 = __half22float2(yz1);
            u64 Z0 = pk2(f0.x, f0.y);
            u64 Z1 = pk2(f1.x, f1.y);
            u64 fz2 = pk2(fzb, fzb);
            u64 d = fma2_(neg12, Z0, Z1);
            acc = fma2_(fz2, d, fma2_(one2, Z0, acc));
        }
    }
    if (i < intEnd) {
        float t = fmaf((float)i + 0.5f, STEP, T0);
        interp1(g, fmaf(fdx, t, cx), fmaf(fdy, t, cy), fmaf(dz, t, cz),
                one2, neg12, acc);
        i++;
    }

    // ---- trailing edge samples ----
    for (int j = max(intEnd, sBeg); j < sEnd; j++) {
        if (j >= intBeg && j < intEnd) continue;
        float t = fmaf((float)j + 0.5f, STEP, T0);
        interp_edge(g, fmaf(fdx, t, cx), fmaf(fdy, t, cy), fmaf(dz, t, cz),
                    one2, neg12, acc);
    }

    float acc0, acc1;
    asm("mov.b64 {%0, %1}, %2;" : "=f"(acc0), "=f"(acc1) : "l"(acc));

    atomicAdd(&out[idx],        acc0 * STEP);
    atomicAdd(&out[idx + NRAY], acc1 * STEP);
}

extern "C" void kernel_launch(void* const* d_in, const int* in_sizes, int n_in,
                              void* d_out, int out_size) {
    const float* vol = (const float*)d_in[0];
    float* out = (float*)d_out;

    {
        dim3 grid(NX / 32, NY / 32, NZ / 2);   // (3,3,48)
        prep_tiled<<<grid, 256>>>(vol, (float4*)out);
    }
    {
        dim3 grid(NRAY / 256, 2);          // (1728, 2)
        fp_kernel<<<grid, 256>>>(out);
    }
}